// round 1
// baseline (speedup 1.0000x reference)
#include <cuda_runtime.h>
#include <math.h>
#include <stdint.h>

// Problem constants
#define BB   4
#define TT   16
#define HH   32
#define WW   32
#define CC   512
#define GG   16
#define CPG  32          // channels per group
#define THW  16384       // TT*HH*WW
#define MTOT 65536       // BB*THW
#define EPSV 1e-6f

// ---------------------------------------------------------------------------
// Scratch (device globals: no allocations allowed)
// ---------------------------------------------------------------------------
__device__ float g_q[(size_t)MTOT * CC];
__device__ float g_k[(size_t)MTOT * CC];
__device__ float g_v[(size_t)MTOT * CC];
__device__ float g_o[(size_t)MTOT * CC];
__device__ float g_part[64 * 8 * 2];     // [b*G+g][slice][{sum,sumsq}]
__device__ float g_scale[BB * CC];       // per (b, channel) affine fold
__device__ float g_shift[BB * CC];

// ---------------------------------------------------------------------------
// Kernel 1: partial GroupNorm statistics.
// grid = 512 blocks: block = (bg, slice); 256 threads.
// Deterministic 2-stage reduction (no atomics).
// ---------------------------------------------------------------------------
__global__ __launch_bounds__(256) void k_stats(const float* __restrict__ x) {
    const int blk   = blockIdx.x;      // 0..511
    const int bg    = blk >> 3;        // 0..63
    const int slice = blk & 7;         // 0..7
    const int b = bg >> 4, g = bg & 15;
    const float* base = x + (size_t)b * THW * CC + g * CPG;

    const int c = threadIdx.x & 31;    // channel within group
    const int w = threadIdx.x >> 5;    // warp id 0..7
    const int p0 = slice * 2048;

    float s = 0.f, ss = 0.f;
    for (int p = w; p < 2048; p += 8) {
        float v = base[(size_t)(p0 + p) * CC + c];   // warp reads 128B contiguous
        s += v; ss += v * v;
    }
    __shared__ float sh0[256], sh1[256];
    sh0[threadIdx.x] = s; sh1[threadIdx.x] = ss;
    __syncthreads();
    for (int st = 128; st > 0; st >>= 1) {
        if (threadIdx.x < st) {
            sh0[threadIdx.x] += sh0[threadIdx.x + st];
            sh1[threadIdx.x] += sh1[threadIdx.x + st];
        }
        __syncthreads();
    }
    if (threadIdx.x == 0) {
        g_part[blk * 2 + 0] = sh0[0];
        g_part[blk * 2 + 1] = sh1[0];
    }
}

// ---------------------------------------------------------------------------
// Kernel 2: finish stats, fold GroupNorm affine into per-(b,channel) scale/shift.
// grid = 8 x 256 threads = 2048 = BB*CC
// ---------------------------------------------------------------------------
__global__ __launch_bounds__(256) void k_scaleshift(const float* __restrict__ gamma,
                                                    const float* __restrict__ beta) {
    const int idx = blockIdx.x * 256 + threadIdx.x;  // 0..2047
    const int b = idx >> 9, ch = idx & 511;
    const int g = ch >> 5;
    const int bg = b * 16 + g;
    float s = 0.f, ss = 0.f;
    #pragma unroll
    for (int sl = 0; sl < 8; sl++) {
        s  += g_part[(bg * 8 + sl) * 2 + 0];
        ss += g_part[(bg * 8 + sl) * 2 + 1];
    }
    const float N = (float)(CPG * THW);
    const float mean = s / N;
    const float var  = ss / N - mean * mean;
    const float inv  = rsqrtf(var + EPSV);
    const float ga   = gamma[ch];
    g_scale[idx] = inv * ga;
    g_shift[idx] = beta[ch] - mean * inv * ga;
}

// ---------------------------------------------------------------------------
// Tiled SGEMM body: C[m,n] = sum_k A'[m,k] * W[n,k] + bias[n]
//   A' = A * scale + shift when NORM (GroupNorm folded into A load)
//   TOUT: write transposed layout out[b*C*THW + n*THW + (m % THW)]
// BM=BN=128, BK=8, 256 threads, 8x8 per-thread tile.
// ---------------------------------------------------------------------------
template <bool NORM, bool TOUT>
__device__ __forceinline__ void gemm_body(const float* __restrict__ A,
                                          const float* __restrict__ W,
                                          const float* __restrict__ bias,
                                          float* __restrict__ O) {
    __shared__ float As[8][128];
    __shared__ float Bs[8][128];

    const int tid = threadIdx.x;
    const int tx  = tid & 15;          // column group 0..15
    const int ty  = tid >> 4;          // row group    0..15
    const int m0  = blockIdx.y * 128;
    const int n0  = blockIdx.x * 128;
    const int lrow = tid >> 1;         // 0..127
    const int lk   = (tid & 1) * 4;    // 0 or 4
    const int bsel = m0 / THW;         // constant per block (THW % 128 == 0)

    const float* aptr = A + (size_t)(m0 + lrow) * CC + lk;
    const float* wptr = W + (size_t)(n0 + lrow) * CC + lk;
    const float* scp  = g_scale + bsel * CC + lk;
    const float* shp  = g_shift + bsel * CC + lk;

    float acc[8][8];
    #pragma unroll
    for (int i = 0; i < 8; i++)
        #pragma unroll
        for (int j = 0; j < 8; j++) acc[i][j] = 0.f;

    for (int k0 = 0; k0 < CC; k0 += 8) {
        float4 a4 = *(const float4*)(aptr + k0);
        if (NORM) {
            float4 s4 = *(const float4*)(scp + k0);
            float4 h4 = *(const float4*)(shp + k0);
            a4.x = fmaf(a4.x, s4.x, h4.x);
            a4.y = fmaf(a4.y, s4.y, h4.y);
            a4.z = fmaf(a4.z, s4.z, h4.z);
            a4.w = fmaf(a4.w, s4.w, h4.w);
        }
        float4 b4 = *(const float4*)(wptr + k0);
        As[lk + 0][lrow] = a4.x; As[lk + 1][lrow] = a4.y;
        As[lk + 2][lrow] = a4.z; As[lk + 3][lrow] = a4.w;
        Bs[lk + 0][lrow] = b4.x; Bs[lk + 1][lrow] = b4.y;
        Bs[lk + 2][lrow] = b4.z; Bs[lk + 3][lrow] = b4.w;
        __syncthreads();
        #pragma unroll
        for (int kk = 0; kk < 8; kk++) {
            float af[8], bf[8];
            *(float4*)(af + 0) = *(const float4*)&As[kk][ty * 8 + 0];
            *(float4*)(af + 4) = *(const float4*)&As[kk][ty * 8 + 4];
            *(float4*)(bf + 0) = *(const float4*)&Bs[kk][tx * 8 + 0];
            *(float4*)(bf + 4) = *(const float4*)&Bs[kk][tx * 8 + 4];
            #pragma unroll
            for (int i = 0; i < 8; i++)
                #pragma unroll
                for (int j = 0; j < 8; j++)
                    acc[i][j] = fmaf(af[i], bf[j], acc[i][j]);
        }
        __syncthreads();
    }

    float bs[8];
    #pragma unroll
    for (int j = 0; j < 8; j++) bs[j] = __ldg(bias + n0 + tx * 8 + j);

    if (!TOUT) {
        #pragma unroll
        for (int i = 0; i < 8; i++) {
            const int m = m0 + ty * 8 + i;
            float* dst = O + (size_t)m * CC + n0 + tx * 8;
            *(float4*)(dst + 0) = make_float4(acc[i][0] + bs[0], acc[i][1] + bs[1],
                                              acc[i][2] + bs[2], acc[i][3] + bs[3]);
            *(float4*)(dst + 4) = make_float4(acc[i][4] + bs[4], acc[i][5] + bs[5],
                                              acc[i][6] + bs[6], acc[i][7] + bs[7]);
        }
    } else {
        // out[b, n, thw]: contiguous along m within a batch
        const int thw0 = m0 % THW;
        const size_t obase = (size_t)bsel * CC * THW + thw0 + ty * 8;
        #pragma unroll
        for (int j = 0; j < 8; j++) {
            const int n = n0 + tx * 8 + j;
            const float bj = bs[j];
            float* col = O + obase + (size_t)n * THW;
            *(float4*)(col + 0) = make_float4(acc[0][j] + bj, acc[1][j] + bj,
                                              acc[2][j] + bj, acc[3][j] + bj);
            *(float4*)(col + 4) = make_float4(acc[4][j] + bj, acc[5][j] + bj,
                                              acc[6][j] + bj, acc[7][j] + bj);
        }
    }
}

__global__ __launch_bounds__(256) void k_gemm_qkv(const float* __restrict__ x,
    const float* __restrict__ wq, const float* __restrict__ bq,
    const float* __restrict__ wk, const float* __restrict__ bk,
    const float* __restrict__ wv, const float* __restrict__ bv) {
    const float* W; const float* bias; float* O;
    if (blockIdx.z == 0)      { W = wq; bias = bq; O = g_q; }
    else if (blockIdx.z == 1) { W = wk; bias = bk; O = g_k; }
    else                      { W = wv; bias = bv; O = g_v; }
    gemm_body<true, false>(x, W, bias, O);
}

__global__ __launch_bounds__(256) void k_gemm_proj(const float* __restrict__ wp,
                                                   const float* __restrict__ bp,
                                                   float* __restrict__ out) {
    gemm_body<false, true>(g_o, wp, bp, out);
}

// ---------------------------------------------------------------------------
// Kernel 4: temporal attention per (b,h,w). T=16, C=512.
// grid = 4096 blocks, 256 threads.
// ---------------------------------------------------------------------------
__global__ __launch_bounds__(256) void k_attn() {
    const int tid = threadIdx.x;
    const int bid = blockIdx.x;          // 0..4095
    const int b  = bid >> 10;
    const int hw = bid & 1023;
    const size_t mbase = (size_t)b * THW + hw;   // m_t = mbase + t*1024

    __shared__ float qs[16][512];
    __shared__ float kv[16][132];        // padded stride (132 words, 16B aligned rows)
    __shared__ float sc[16][16];

    // load all of q (16 x 512) into smem
    #pragma unroll
    for (int it = 0; it < 8; it++) {
        const int idx4 = tid + it * 256;       // 0..2047 float4s
        const int t  = idx4 >> 7;
        const int c4 = idx4 & 127;
        *(float4*)&qs[t][c4 * 4] =
            *(const float4*)&g_q[(mbase + (size_t)t * 1024) * CC + c4 * 4];
    }
    __syncthreads();

    // scores: one (t1,t2) pair per thread; k streamed through smem in 128-col chunks
    const int t1 = tid >> 4;
    const int t2 = tid & 15;
    float s = 0.f;
    for (int ch = 0; ch < 4; ch++) {
        #pragma unroll
        for (int it = 0; it < 2; it++) {
            const int idx4 = tid + it * 256;   // 0..511
            const int t  = idx4 >> 5;
            const int c4 = idx4 & 31;
            *(float4*)&kv[t][c4 * 4] =
                *(const float4*)&g_k[(mbase + (size_t)t * 1024) * CC + ch * 128 + c4 * 4];
        }
        __syncthreads();
        #pragma unroll
        for (int c4 = 0; c4 < 32; c4++) {
            float4 q4 = *(const float4*)&qs[t1][ch * 128 + c4 * 4];
            float4 k4 = *(const float4*)&kv[t2][c4 * 4];
            s += q4.x * k4.x + q4.y * k4.y + q4.z * k4.z + q4.w * k4.w;
        }
        __syncthreads();
    }
    sc[t1][t2] = s * 0.044194173824159216f;   // 512^-0.5
    __syncthreads();

    // softmax over t2, one row per thread (threads 0..15)
    if (tid < 16) {
        float mx = -1e30f;
        #pragma unroll
        for (int j = 0; j < 16; j++) mx = fmaxf(mx, sc[tid][j]);
        float e[16], sum = 0.f;
        #pragma unroll
        for (int j = 0; j < 16; j++) { e[j] = expf(sc[tid][j] - mx); sum += e[j]; }
        const float r = 1.f / sum;
        #pragma unroll
        for (int j = 0; j < 16; j++) sc[tid][j] = e[j] * r;
    }
    __syncthreads();

    // o = attn @ v, v streamed through smem chunks
    const int ot = tid >> 4;
    const int cg = tid & 15;
    for (int ch = 0; ch < 4; ch++) {
        #pragma unroll
        for (int it = 0; it < 2; it++) {
            const int idx4 = tid + it * 256;
            const int t  = idx4 >> 5;
            const int c4 = idx4 & 31;
            *(float4*)&kv[t][c4 * 4] =
                *(const float4*)&g_v[(mbase + (size_t)t * 1024) * CC + ch * 128 + c4 * 4];
        }
        __syncthreads();
        float o8[8];
        #pragma unroll
        for (int cc = 0; cc < 8; cc++) {
            float a = 0.f;
            #pragma unroll
            for (int j = 0; j < 16; j++) a = fmaf(sc[ot][j], kv[j][cg * 8 + cc], a);
            o8[cc] = a;
        }
        float* dst = &g_o[(mbase + (size_t)ot * 1024) * CC + ch * 128 + cg * 8];
        *(float4*)(dst + 0) = make_float4(o8[0], o8[1], o8[2], o8[3]);
        *(float4*)(dst + 4) = make_float4(o8[4], o8[5], o8[6], o8[7]);
        __syncthreads();
    }
}

// ---------------------------------------------------------------------------
// Launch
// ---------------------------------------------------------------------------
extern "C" void kernel_launch(void* const* d_in, const int* in_sizes, int n_in,
                              void* d_out, int out_size) {
    const float* x     = (const float*)d_in[0];
    const float* gamma = (const float*)d_in[1];
    const float* beta  = (const float*)d_in[2];
    const float* wq = (const float*)d_in[3];  const float* bq = (const float*)d_in[4];
    const float* wk = (const float*)d_in[5];  const float* bk = (const float*)d_in[6];
    const float* wv = (const float*)d_in[7];  const float* bv = (const float*)d_in[8];
    const float* wp = (const float*)d_in[9];  const float* bp = (const float*)d_in[10];
    float* out = (float*)d_out;

    k_stats<<<512, 256>>>(x);
    k_scaleshift<<<8, 256>>>(gamma, beta);
    k_gemm_qkv<<<dim3(4, 512, 3), 256>>>(x, wq, bq, wk, bk, wv, bv);
    k_attn<<<4096, 256>>>();
    k_gemm_proj<<<dim3(4, 512), 256>>>(wp, bp, out);
}

// round 2
// speedup vs baseline: 2.2201x; 2.2201x over previous
#include <cuda_runtime.h>
#include <math.h>
#include <stdint.h>

// Problem constants
#define BB   4
#define TT   16
#define HH   32
#define WW   32
#define CC   512
#define GG   16
#define CPG  32
#define THW  16384       // TT*HH*WW
#define MTOT 65536       // BB*THW
#define EPSV 1e-6f

// GEMM tiling
#define BM 128
#define BN 128
#define BK 16
#define PAD 8            // smem row pitch 136 -> conflict-free fragment loads

// ---------------------------------------------------------------------------
// Scratch (device globals: no allocations allowed)
// ---------------------------------------------------------------------------
__device__ float g_q[(size_t)MTOT * CC];
__device__ float g_k[(size_t)MTOT * CC];
__device__ float g_v[(size_t)MTOT * CC];
__device__ float g_o[(size_t)MTOT * CC];
__device__ float g_part[64 * 8 * 2];
__device__ float g_scale[BB * CC];
__device__ float g_shift[BB * CC];
__device__ float g_wfold[12 * 512 * 512];   // [z*4+b][n][k] scaled weights
__device__ float g_bfold[12 * 512];         // folded biases

// ---------------------------------------------------------------------------
// Kernel 1: partial GroupNorm statistics (deterministic, no atomics)
// ---------------------------------------------------------------------------
__global__ __launch_bounds__(256) void k_stats(const float* __restrict__ x) {
    const int blk   = blockIdx.x;      // 0..511
    const int bg    = blk >> 3;
    const int slice = blk & 7;
    const int b = bg >> 4, g = bg & 15;
    const float* base = x + (size_t)b * THW * CC + g * CPG;

    const int c = threadIdx.x & 31;
    const int w = threadIdx.x >> 5;
    const int p0 = slice * 2048;

    float s = 0.f, ss = 0.f;
    for (int p = w; p < 2048; p += 8) {
        float v = base[(size_t)(p0 + p) * CC + c];
        s += v; ss += v * v;
    }
    __shared__ float sh0[256], sh1[256];
    sh0[threadIdx.x] = s; sh1[threadIdx.x] = ss;
    __syncthreads();
    for (int st = 128; st > 0; st >>= 1) {
        if (threadIdx.x < st) {
            sh0[threadIdx.x] += sh0[threadIdx.x + st];
            sh1[threadIdx.x] += sh1[threadIdx.x + st];
        }
        __syncthreads();
    }
    if (threadIdx.x == 0) {
        g_part[blk * 2 + 0] = sh0[0];
        g_part[blk * 2 + 1] = sh1[0];
    }
}

// ---------------------------------------------------------------------------
// Kernel 2: finish stats -> per (b,channel) scale/shift
// ---------------------------------------------------------------------------
__global__ __launch_bounds__(256) void k_scaleshift(const float* __restrict__ gamma,
                                                    const float* __restrict__ beta) {
    const int idx = blockIdx.x * 256 + threadIdx.x;
    const int b = idx >> 9, ch = idx & 511;
    const int g = ch >> 5;
    const int bg = b * 16 + g;
    float s = 0.f, ss = 0.f;
    #pragma unroll
    for (int sl = 0; sl < 8; sl++) {
        s  += g_part[(bg * 8 + sl) * 2 + 0];
        ss += g_part[(bg * 8 + sl) * 2 + 1];
    }
    const float N = (float)(CPG * THW);
    const float mean = s / N;
    const float var  = ss / N - mean * mean;
    const float inv  = rsqrtf(var + EPSV);
    const float ga   = gamma[ch];
    g_scale[idx] = inv * ga;
    g_shift[idx] = beta[ch] - mean * inv * ga;
}

// ---------------------------------------------------------------------------
// Kernel 3: fold GroupNorm into weights/biases.
//   W'[z,b][n][k] = W_z[n][k] * scale[b][k]
//   b'[z,b][n]    = b_z[n] + sum_k shift[b][k] * W_z[n][k]
// grid = 3*4*512 blocks, 128 threads (one output row each)
// ---------------------------------------------------------------------------
__global__ __launch_bounds__(128) void k_foldw(
    const float* __restrict__ wq, const float* __restrict__ bq,
    const float* __restrict__ wk, const float* __restrict__ bk,
    const float* __restrict__ wv, const float* __restrict__ bv) {
    const int id = blockIdx.x;
    const int z = id >> 11;
    const int b = (id >> 9) & 3;
    const int n = id & 511;
    const float* W; const float* bi;
    if (z == 0)      { W = wq; bi = bq; }
    else if (z == 1) { W = wk; bi = bk; }
    else             { W = wv; bi = bv; }
    const float* wr = W + (size_t)n * 512;
    const float* sc = g_scale + b * 512;
    const float* sh = g_shift + b * 512;
    float* wo = g_wfold + ((size_t)(z * 4 + b) * 512 + n) * 512;

    float acc = 0.f;
    for (int k = threadIdx.x; k < 512; k += 128) {
        float w = wr[k];
        wo[k] = w * sc[k];
        acc += w * sh[k];
    }
    __shared__ float red[128];
    red[threadIdx.x] = acc; __syncthreads();
    for (int st = 64; st > 0; st >>= 1) {
        if (threadIdx.x < st) red[threadIdx.x] += red[threadIdx.x + st];
        __syncthreads();
    }
    if (threadIdx.x == 0) g_bfold[(z * 4 + b) * 512 + n] = bi[n] + red[0];
}

// ---------------------------------------------------------------------------
// tf32 tensor-core GEMM body.
//   D[m][n] = sum_k A[m][k] * B[n][k]   (both row-major, k contiguous)
//   BIASM ? bias indexed by m (row) : by n (col)
//   output row stride = ldo
// ---------------------------------------------------------------------------
__device__ __forceinline__ float cvt_tf32(float x) {
    uint32_t u; asm("cvt.rna.tf32.f32 %0, %1;" : "=r"(u) : "f"(x));
    return __uint_as_float(u);
}

__device__ __forceinline__ void mma8(float (&d)[4], const uint32_t (&a)[4],
                                     const uint32_t (&b)[2]) {
    asm volatile("mma.sync.aligned.m16n8k8.row.col.f32.tf32.tf32.f32 "
        "{%0,%1,%2,%3}, {%4,%5,%6,%7}, {%8,%9}, {%0,%1,%2,%3};\n"
        : "+f"(d[0]), "+f"(d[1]), "+f"(d[2]), "+f"(d[3])
        : "r"(a[0]), "r"(a[1]), "r"(a[2]), "r"(a[3]), "r"(b[0]), "r"(b[1]));
}

template <bool BIASM>
__device__ __forceinline__ void gemm_tc(const float* __restrict__ Abase,
                                        const float* __restrict__ Bbase,
                                        const float* __restrict__ bias,
                                        float* __restrict__ obase, int ldo) {
    __shared__ float As[2][BK][BM + PAD];
    __shared__ float Bs[2][BK][BN + PAD];

    const int tid = threadIdx.x;
    const int wid = tid >> 5, lane = tid & 31;
    const int g = lane >> 2, tig = lane & 3;
    const int wm = (wid >> 2) * 64;    // warp m offset: 0/64
    const int wn = (wid & 3) * 32;     // warp n offset: 0/32/64/96
    const int lr = tid >> 1;           // 0..127 (row loaded by this thread)
    const int lk = (tid & 1) * 8;      // 0 or 8

    const float* aptr = Abase + (size_t)lr * CC + lk;
    const float* bptr = Bbase + (size_t)lr * CC + lk;

    float acc[4][4][4];
    #pragma unroll
    for (int mt = 0; mt < 4; mt++)
        #pragma unroll
        for (int nt = 0; nt < 4; nt++)
            #pragma unroll
            for (int r = 0; r < 4; r++) acc[mt][nt][r] = 0.f;

    float4 ra0 = *(const float4*)(aptr);
    float4 ra1 = *(const float4*)(aptr + 4);
    float4 rb0 = *(const float4*)(bptr);
    float4 rb1 = *(const float4*)(bptr + 4);

    As[0][lk+0][lr]=cvt_tf32(ra0.x); As[0][lk+1][lr]=cvt_tf32(ra0.y);
    As[0][lk+2][lr]=cvt_tf32(ra0.z); As[0][lk+3][lr]=cvt_tf32(ra0.w);
    As[0][lk+4][lr]=cvt_tf32(ra1.x); As[0][lk+5][lr]=cvt_tf32(ra1.y);
    As[0][lk+6][lr]=cvt_tf32(ra1.z); As[0][lk+7][lr]=cvt_tf32(ra1.w);
    Bs[0][lk+0][lr]=cvt_tf32(rb0.x); Bs[0][lk+1][lr]=cvt_tf32(rb0.y);
    Bs[0][lk+2][lr]=cvt_tf32(rb0.z); Bs[0][lk+3][lr]=cvt_tf32(rb0.w);
    Bs[0][lk+4][lr]=cvt_tf32(rb1.x); Bs[0][lk+5][lr]=cvt_tf32(rb1.y);
    Bs[0][lk+6][lr]=cvt_tf32(rb1.z); Bs[0][lk+7][lr]=cvt_tf32(rb1.w);
    __syncthreads();

    const int NS = CC / BK;   // 32
    #pragma unroll 1
    for (int s = 0; s < NS; s++) {
        const int cur = s & 1;
        if (s + 1 < NS) {
            const float* ap = aptr + (s + 1) * BK;
            ra0 = *(const float4*)(ap);
            ra1 = *(const float4*)(ap + 4);
            const float* bp = bptr + (s + 1) * BK;
            rb0 = *(const float4*)(bp);
            rb1 = *(const float4*)(bp + 4);
        }
        #pragma unroll
        for (int ks = 0; ks < 2; ks++) {
            const int kb = ks * 8;
            uint32_t af[4][4], bfr[4][2];
            #pragma unroll
            for (int mt = 0; mt < 4; mt++) {
                const int m = wm + mt * 16 + g;
                af[mt][0] = __float_as_uint(As[cur][kb + tig    ][m]);
                af[mt][1] = __float_as_uint(As[cur][kb + tig    ][m + 8]);
                af[mt][2] = __float_as_uint(As[cur][kb + tig + 4][m]);
                af[mt][3] = __float_as_uint(As[cur][kb + tig + 4][m + 8]);
            }
            #pragma unroll
            for (int nt = 0; nt < 4; nt++) {
                const int n = wn + nt * 8 + g;
                bfr[nt][0] = __float_as_uint(Bs[cur][kb + tig    ][n]);
                bfr[nt][1] = __float_as_uint(Bs[cur][kb + tig + 4][n]);
            }
            #pragma unroll
            for (int mt = 0; mt < 4; mt++)
                #pragma unroll
                for (int nt = 0; nt < 4; nt++)
                    mma8(acc[mt][nt], af[mt], bfr[nt]);
        }
        if (s + 1 < NS) {
            const int nb = (s + 1) & 1;
            As[nb][lk+0][lr]=cvt_tf32(ra0.x); As[nb][lk+1][lr]=cvt_tf32(ra0.y);
            As[nb][lk+2][lr]=cvt_tf32(ra0.z); As[nb][lk+3][lr]=cvt_tf32(ra0.w);
            As[nb][lk+4][lr]=cvt_tf32(ra1.x); As[nb][lk+5][lr]=cvt_tf32(ra1.y);
            As[nb][lk+6][lr]=cvt_tf32(ra1.z); As[nb][lk+7][lr]=cvt_tf32(ra1.w);
            Bs[nb][lk+0][lr]=cvt_tf32(rb0.x); Bs[nb][lk+1][lr]=cvt_tf32(rb0.y);
            Bs[nb][lk+2][lr]=cvt_tf32(rb0.z); Bs[nb][lk+3][lr]=cvt_tf32(rb0.w);
            Bs[nb][lk+4][lr]=cvt_tf32(rb1.x); Bs[nb][lk+5][lr]=cvt_tf32(rb1.y);
            Bs[nb][lk+6][lr]=cvt_tf32(rb1.z); Bs[nb][lk+7][lr]=cvt_tf32(rb1.w);
        }
        __syncthreads();
    }

    // Epilogue: c0/c1 contiguous along n -> float2 stores
    #pragma unroll
    for (int mt = 0; mt < 4; mt++) {
        const int r0 = wm + mt * 16 + g;
        float br0 = 0.f, br1 = 0.f;
        if (BIASM) { br0 = __ldg(bias + r0); br1 = __ldg(bias + r0 + 8); }
        #pragma unroll
        for (int nt = 0; nt < 4; nt++) {
            const int c0 = wn + nt * 8 + 2 * tig;
            float bc0 = 0.f, bc1 = 0.f;
            if (!BIASM) { bc0 = __ldg(bias + c0); bc1 = __ldg(bias + c0 + 1); }
            const float a0 = BIASM ? br0 : bc0, a1 = BIASM ? br0 : bc1;
            const float a2 = BIASM ? br1 : bc0, a3 = BIASM ? br1 : bc1;
            *(float2*)(obase + (size_t)r0 * ldo + c0) =
                make_float2(acc[mt][nt][0] + a0, acc[mt][nt][1] + a1);
            *(float2*)(obase + (size_t)(r0 + 8) * ldo + c0) =
                make_float2(acc[mt][nt][2] + a2, acc[mt][nt][3] + a3);
        }
    }
}

__global__ __launch_bounds__(256, 2) void k_gemm_qkv(const float* __restrict__ x) {
    const int n0 = blockIdx.x * BN;
    const int m0 = blockIdx.y * BM;
    const int z  = blockIdx.z;
    const int bsel = m0 / THW;
    const float* Bb = g_wfold + (size_t)(z * 4 + bsel) * 512 * 512 + (size_t)n0 * CC;
    const float* bi = g_bfold + (z * 4 + bsel) * 512 + n0;
    float* O = (z == 0 ? g_q : z == 1 ? g_k : g_v);
    gemm_tc<false>(x + (size_t)m0 * CC, Bb, bi, O + (size_t)m0 * CC + n0, CC);
}

__global__ __launch_bounds__(256, 2) void k_gemm_proj(const float* __restrict__ wp,
                                                      const float* __restrict__ bp,
                                                      float* __restrict__ out) {
    const int mc0 = blockIdx.x * BM;         // out-channel tile
    const int yy  = blockIdx.y;
    const int bsel = yy >> 7;
    const int thw0 = (yy & 127) * BN;
    const float* Ab = wp + (size_t)mc0 * CC;
    const float* Bb = g_o + ((size_t)bsel * THW + thw0) * CC;
    float* ob = out + (size_t)bsel * CC * THW + (size_t)mc0 * THW + thw0;
    gemm_tc<true>(Ab, Bb, bp + mc0, ob, THW);
}

// ---------------------------------------------------------------------------
// Kernel 5: temporal attention per (b,h,w). T=16, C=512.
// ---------------------------------------------------------------------------
__global__ __launch_bounds__(256) void k_attn() {
    const int tid = threadIdx.x;
    const int bid = blockIdx.x;
    const int b  = bid >> 10;
    const int hw = bid & 1023;
    const size_t mbase = (size_t)b * THW + hw;

    __shared__ float qs[16][512];
    __shared__ float kv[16][132];
    __shared__ float sc[16][16];

    #pragma unroll
    for (int it = 0; it < 8; it++) {
        const int idx4 = tid + it * 256;
        const int t  = idx4 >> 7;
        const int c4 = idx4 & 127;
        *(float4*)&qs[t][c4 * 4] =
            *(const float4*)&g_q[(mbase + (size_t)t * 1024) * CC + c4 * 4];
    }
    __syncthreads();

    const int t1 = tid >> 4;
    const int t2 = tid & 15;
    float s = 0.f;
    for (int ch = 0; ch < 4; ch++) {
        #pragma unroll
        for (int it = 0; it < 2; it++) {
            const int idx4 = tid + it * 256;
            const int t  = idx4 >> 5;
            const int c4 = idx4 & 31;
            *(float4*)&kv[t][c4 * 4] =
                *(const float4*)&g_k[(mbase + (size_t)t * 1024) * CC + ch * 128 + c4 * 4];
        }
        __syncthreads();
        #pragma unroll
        for (int c4 = 0; c4 < 32; c4++) {
            float4 q4 = *(const float4*)&qs[t1][ch * 128 + c4 * 4];
            float4 k4 = *(const float4*)&kv[t2][c4 * 4];
            s += q4.x * k4.x + q4.y * k4.y + q4.z * k4.z + q4.w * k4.w;
        }
        __syncthreads();
    }
    sc[t1][t2] = s * 0.044194173824159216f;
    __syncthreads();

    if (tid < 16) {
        float mx = -1e30f;
        #pragma unroll
        for (int j = 0; j < 16; j++) mx = fmaxf(mx, sc[tid][j]);
        float e[16], sum = 0.f;
        #pragma unroll
        for (int j = 0; j < 16; j++) { e[j] = expf(sc[tid][j] - mx); sum += e[j]; }
        const float r = 1.f / sum;
        #pragma unroll
        for (int j = 0; j < 16; j++) sc[tid][j] = e[j] * r;
    }
    __syncthreads();

    const int ot = tid >> 4;
    const int cg = tid & 15;
    for (int ch = 0; ch < 4; ch++) {
        #pragma unroll
        for (int it = 0; it < 2; it++) {
            const int idx4 = tid + it * 256;
            const int t  = idx4 >> 5;
            const int c4 = idx4 & 31;
            *(float4*)&kv[t][c4 * 4] =
                *(const float4*)&g_v[(mbase + (size_t)t * 1024) * CC + ch * 128 + c4 * 4];
        }
        __syncthreads();
        float o8[8];
        #pragma unroll
        for (int cc = 0; cc < 8; cc++) {
            float a = 0.f;
            #pragma unroll
            for (int j = 0; j < 16; j++) a = fmaf(sc[ot][j], kv[j][cg * 8 + cc], a);
            o8[cc] = a;
        }
        float* dst = &g_o[(mbase + (size_t)ot * 1024) * CC + ch * 128 + cg * 8];
        *(float4*)(dst + 0) = make_float4(o8[0], o8[1], o8[2], o8[3]);
        *(float4*)(dst + 4) = make_float4(o8[4], o8[5], o8[6], o8[7]);
        __syncthreads();
    }
}

// ---------------------------------------------------------------------------
// Launch
// ---------------------------------------------------------------------------
extern "C" void kernel_launch(void* const* d_in, const int* in_sizes, int n_in,
                              void* d_out, int out_size) {
    const float* x     = (const float*)d_in[0];
    const float* gamma = (const float*)d_in[1];
    const float* beta  = (const float*)d_in[2];
    const float* wq = (const float*)d_in[3];  const float* bq = (const float*)d_in[4];
    const float* wk = (const float*)d_in[5];  const float* bk = (const float*)d_in[6];
    const float* wv = (const float*)d_in[7];  const float* bv = (const float*)d_in[8];
    const float* wp = (const float*)d_in[9];  const float* bp = (const float*)d_in[10];
    float* out = (float*)d_out;

    k_stats<<<512, 256>>>(x);
    k_scaleshift<<<8, 256>>>(gamma, beta);
    k_foldw<<<3 * 4 * 512, 128>>>(wq, bq, wk, bk, wv, bv);
    k_gemm_qkv<<<dim3(4, 512, 3), 256>>>(x);
    k_attn<<<4096, 256>>>();
    k_gemm_proj<<<dim3(4, 512), 256>>>(wp, bp, out);
}